// round 9
// baseline (speedup 1.0000x reference)
#include <cuda_runtime.h>
#include <cuda_bf16.h>

// Problem dims (fixed by the reference):
// B=2, G=8, D=32, H=128, W=160, NEIGH=9 (3x3), PAD1=2, PAD2=4
#define B_  2
#define G_  8
#define D_  32
#define H_  128
#define W_  160
#define HW_ (H_*W_)          // 20480
#define DHW_ (D_*HW_)        // 655360
#define N1_ (B_*DHW_)        // 1310720  (sim / output elements)

typedef unsigned long long u64;

// Scratch for the per-pixel similarity map (B, D, H, W) fp32 = 5.24 MB
__device__ float g_sim[N1_];

// ---------------------------------------------------------------------------
// Packed f32x2 helpers (Blackwell sm_103a)
// ---------------------------------------------------------------------------
__device__ __forceinline__ u64 pk2(float lo, float hi) {
    u64 r; asm("mov.b64 %0, {%1, %2};" : "=l"(r) : "f"(lo), "f"(hi)); return r;
}
__device__ __forceinline__ void upk2(u64 v, float& lo, float& hi) {
    asm("mov.b64 {%0, %1}, %2;" : "=f"(lo), "=f"(hi) : "l"(v));
}
__device__ __forceinline__ u64 fma2(u64 a, u64 b, u64 c) {
    u64 d; asm("fma.rn.f32x2 %0, %1, %2, %3;" : "=l"(d) : "l"(a), "l"(b), "l"(c)); return d;
}
__device__ __forceinline__ u64 mul2(u64 a, u64 b) {
    u64 d; asm("mul.rn.f32x2 %0, %1, %2;" : "=l"(d) : "l"(a), "l"(b)); return d;
}
__device__ __forceinline__ u64 relu2(u64 v) {
    float a, b; upk2(v, a, b);
    return pk2(fmaxf(a, 0.0f), fmaxf(b, 0.0f));
}

// ---------------------------------------------------------------------------
// Kernel 1: per-pixel MLP, 2 pixels per thread, f32x2 packed math.
// Low register footprint -> high occupancy; x pairs loaded directly as u64.
// sim = w_sim . relu( bn1(W1 . relu( bn0(W0 . x) )) ) + b_sim
// ---------------------------------------------------------------------------
__global__ __launch_bounds__(256)
void mlp_sim_kernel(const float* __restrict__ x1,
                    const float* __restrict__ w0,
                    const float* __restrict__ bn0_scale,
                    const float* __restrict__ bn0_bias,
                    const float* __restrict__ w1,
                    const float* __restrict__ bn1_scale,
                    const float* __restrict__ bn1_bias,
                    const float* __restrict__ w_sim,
                    const float* __restrict__ b_sim)
{
    // sw0p[o*8+g]  = dup2( w0[o][g]  * bn0_scale[o] )   (g contiguous)
    // sw1p[o*8+k]  = dup2( w1[k][o]  * bn1_scale[k] )   (k contiguous)
    __shared__ __align__(16) u64 sw0p[16*8];
    __shared__ __align__(16) u64 sw1p[16*8];
    __shared__ float sb0[16];
    __shared__ float sb1[8];
    __shared__ float sws[8];
    __shared__ float sbs;

    const int t = threadIdx.x;
    if (t < 128) {
        float v = w0[t] * bn0_scale[t >> 3];     // t = o*8+g
        sw0p[t] = pk2(v, v);
    } else {
        int i = t - 128;                         // i = o*8+k
        int o = i >> 3, k = i & 7;
        float v = w1[k * 16 + o] * bn1_scale[k];
        sw1p[i] = pk2(v, v);
    }
    if (t < 16)       sb0[t] = bn0_bias[t];
    else if (t < 24)  sb1[t - 16] = bn1_bias[t - 16];
    else if (t < 32)  sws[t - 24] = w_sim[t - 24];
    else if (t == 32) sbs = b_sim[0];
    __syncthreads();

    const int idx2 = (blockIdx.x * 256 + t) * 2;     // N1_ multiple of 512
    const int b = idx2 / DHW_;                       // pair shares b (DHW_ even)
    const int base = idx2 + b * (G_ - 1) * DHW_;     // x1 flat idx of (b,g=0,pix), even

    const u64* __restrict__ x2 = (const u64*)x1;

    u64 xp[G_];
#pragma unroll
    for (int g = 0; g < G_; g++)
        xp[g] = __ldg(&x2[(base + g * DHW_) >> 1]);  // two consecutive fp32 = f32x2 pack

    u64 h1p[8];
#pragma unroll
    for (int k = 0; k < 8; k++)
        h1p[k] = pk2(sb1[k], sb1[k]);

#pragma unroll
    for (int o = 0; o < 16; o++) {
        u64 a0 = pk2(sb0[o], sb0[o]);
#pragma unroll
        for (int g = 0; g < G_; g += 2) {
            ulonglong2 wv = *(const ulonglong2*)&sw0p[o * 8 + g];  // LDS.128
            a0 = fma2(wv.x, xp[g],     a0);
            a0 = fma2(wv.y, xp[g + 1], a0);
        }
        a0 = relu2(a0);
#pragma unroll
        for (int k = 0; k < 8; k += 2) {
            ulonglong2 wv = *(const ulonglong2*)&sw1p[o * 8 + k];  // LDS.128
            h1p[k]     = fma2(wv.x, a0, h1p[k]);
            h1p[k + 1] = fma2(wv.y, a0, h1p[k + 1]);
        }
    }

    float s_lo = sbs, s_hi = sbs;
#pragma unroll
    for (int k = 0; k < 8; k++) {
        float lo, hi; upk2(h1p[k], lo, hi);
        s_lo = fmaf(sws[k], fmaxf(lo, 0.0f), s_lo);
        s_hi = fmaf(sws[k], fmaxf(hi, 0.0f), s_hi);
    }
    ((u64*)g_sim)[idx2 >> 1] = pk2(s_lo, s_hi);
}

// ---------------------------------------------------------------------------
// Kernel 2: two-scale 3x3 reflect stencil over sim, weighted by offset maps.
// One thread per (b, d-chunk of 2, h, pixel-pair (w0, w0+1)), w0 even.
// DCHUNK=2 -> 10240 warps -> full occupancy for latency hiding.
// ---------------------------------------------------------------------------
#define DCHUNK 2

__device__ __forceinline__ int reflect_idx(int k, int n) {
    if (k < 0) return -k;
    if (k >= n) return 2 * n - 2 - k;
    return k;
}

__global__ __launch_bounds__(128)
void stencil_kernel(const float* __restrict__ offset,
                    const float* __restrict__ weight,
                    float* __restrict__ out)
{
    const int idx = blockIdx.x * 128 + threadIdx.x;   // B*(D/DCHUNK)*H*(W/2)
    const int per_b = (D_ / DCHUNK) * H_ * (W_ / 2);  // 163840
    const int b  = idx / per_b;
    int r        = idx - b * per_b;
    const int dc = r / (H_ * (W_ / 2));
    r           -= dc * (H_ * (W_ / 2));
    const int h  = r / (W_ / 2);
    const int w0 = (r - h * (W_ / 2)) * 2;
    const int hw = h * W_ + w0;

    const u64* __restrict__ off64 = (const u64*)offset;
    const int obase = (b * 18 * HW_ + hw) >> 1;       // u64 index (hw even)

    u64 wgt2;
    {
        float g0, g1;
        upk2(__ldg(&((const u64*)weight)[(b * HW_ + hw) >> 1]), g0, g1);
        wgt2 = pk2(0.5f * g0, 0.5f * g1);
    }

    const int d0 = (b * D_ + dc * DCHUNK) * HW_;
    const u64* __restrict__ simb = (const u64*)g_sim + (d0 >> 1);
    u64* __restrict__ out64 = (u64*)out;

    u64 acc[DCHUNK];
#pragma unroll
    for (int dd = 0; dd < DCHUNK; dd++) acc[dd] = 0ULL;

    const bool interior = (w0 >= 4) && (w0 <= W_ - 6);

    if (interior) {
#pragma unroll 1
        for (int iy = 0; iy < 3; iy++) {
            const int ry1 = reflect_idx(h + 2 * (iy - 1), H_);
            const int ry2 = reflect_idx(h + 4 * (iy - 1), H_);
            const int r1 = (ry1 * W_ + w0) >> 1;      // u64 index of center tap
            const int r2 = (ry2 * W_ + w0) >> 1;
#pragma unroll
            for (int ix = 0; ix < 3; ix++) {
                const int s = iy * 3 + ix;
                const u64 wW = __ldg(&off64[obase + s * (HW_ / 2)]);
                const u64 wN = __ldg(&off64[obase + (s + 9) * (HW_ / 2)]);
#pragma unroll
                for (int dd = 0; dd < DCHUNK; dd++) {
                    const u64* __restrict__ p = simb + dd * (HW_ / 2);
                    acc[dd] = fma2(wN, p[r1 + (ix - 1)],     acc[dd]);
                    acc[dd] = fma2(wW, p[r2 + 2 * (ix - 1)], acc[dd]);
                }
            }
        }
    } else {
        // edge path: scalar reflect in x for both pixels of the pair
        float a0[DCHUNK], a1[DCHUNK];
#pragma unroll
        for (int dd = 0; dd < DCHUNK; dd++) { a0[dd] = 0.0f; a1[dd] = 0.0f; }
#pragma unroll 1
        for (int iy = 0; iy < 3; iy++) {
            const int ro1 = reflect_idx(h + 2 * (iy - 1), H_) * W_;
            const int ro2 = reflect_idx(h + 4 * (iy - 1), H_) * W_;
#pragma unroll
            for (int ix = 0; ix < 3; ix++) {
                const int s = iy * 3 + ix;
                float wW0, wW1, wN0, wN1;
                upk2(__ldg(&off64[obase + s * (HW_ / 2)]), wW0, wW1);
                upk2(__ldg(&off64[obase + (s + 9) * (HW_ / 2)]), wN0, wN1);
                const int x1a = reflect_idx(w0     + 2 * (ix - 1), W_);
                const int x1b = reflect_idx(w0 + 1 + 2 * (ix - 1), W_);
                const int x2a = reflect_idx(w0     + 4 * (ix - 1), W_);
                const int x2b = reflect_idx(w0 + 1 + 4 * (ix - 1), W_);
#pragma unroll
                for (int dd = 0; dd < DCHUNK; dd++) {
                    const float* __restrict__ ps = g_sim + d0 + dd * HW_;
                    a0[dd] = fmaf(wN0, ps[ro1 + x1a], a0[dd]);
                    a0[dd] = fmaf(wW0, ps[ro2 + x2a], a0[dd]);
                    a1[dd] = fmaf(wN1, ps[ro1 + x1b], a1[dd]);
                    a1[dd] = fmaf(wW1, ps[ro2 + x2b], a1[dd]);
                }
            }
        }
#pragma unroll
        for (int dd = 0; dd < DCHUNK; dd++) acc[dd] = pk2(a0[dd], a1[dd]);
    }

#pragma unroll
    for (int dd = 0; dd < DCHUNK; dd++)
        out64[(d0 + dd * HW_ + hw) >> 1] = mul2(acc[dd], wgt2);
}

// ---------------------------------------------------------------------------
// Launch
// ---------------------------------------------------------------------------
extern "C" void kernel_launch(void* const* d_in, const int* in_sizes, int n_in,
                              void* d_out, int out_size)
{
    const float* x1        = (const float*)d_in[0];
    const float* offset    = (const float*)d_in[1];
    const float* weight    = (const float*)d_in[2];
    const float* w0        = (const float*)d_in[3];
    const float* bn0_scale = (const float*)d_in[4];
    const float* bn0_bias  = (const float*)d_in[5];
    const float* w1        = (const float*)d_in[6];
    const float* bn1_scale = (const float*)d_in[7];
    const float* bn1_bias  = (const float*)d_in[8];
    const float* w_sim     = (const float*)d_in[9];
    const float* b_sim     = (const float*)d_in[10];
    float* out = (float*)d_out;

    // Kernel 1: 2 pixels/thread -> 655,360 threads, grid 2560
    mlp_sim_kernel<<<N1_ / (256 * 2), 256>>>(x1, w0, bn0_scale, bn0_bias,
                                             w1, bn1_scale, bn1_bias, w_sim, b_sim);

    // Kernel 2: pixel-pair threads: B*(D/2)*H*(W/2) = 327,680, grid 2560
    const int n2 = B_ * (D_ / DCHUNK) * H_ * (W_ / 2);
    stencil_kernel<<<n2 / 128, 128>>>(offset, weight, out);
}

// round 11
// speedup vs baseline: 1.0008x; 1.0008x over previous
#include <cuda_runtime.h>
#include <cuda_bf16.h>

// Problem dims (fixed by the reference):
// B=2, G=8, D=32, H=128, W=160, NEIGH=9 (3x3), PAD1=2, PAD2=4
#define B_  2
#define G_  8
#define D_  32
#define H_  128
#define W_  160
#define HW_ (H_*W_)          // 20480
#define DHW_ (D_*HW_)        // 655360
#define N1_ (B_*DHW_)        // 1310720  (sim / output elements)

typedef unsigned long long u64;

// Scratch for the per-pixel similarity map (B, D, H, W) fp32 = 5.24 MB
__device__ float g_sim[N1_];

// ---------------------------------------------------------------------------
// Packed f32x2 helpers (Blackwell sm_103a)
// ---------------------------------------------------------------------------
__device__ __forceinline__ u64 pk2(float lo, float hi) {
    u64 r; asm("mov.b64 %0, {%1, %2};" : "=l"(r) : "f"(lo), "f"(hi)); return r;
}
__device__ __forceinline__ void upk2(u64 v, float& lo, float& hi) {
    asm("mov.b64 {%0, %1}, %2;" : "=f"(lo), "=f"(hi) : "l"(v));
}
__device__ __forceinline__ u64 fma2(u64 a, u64 b, u64 c) {
    u64 d; asm("fma.rn.f32x2 %0, %1, %2, %3;" : "=l"(d) : "l"(a), "l"(b), "l"(c)); return d;
}
__device__ __forceinline__ u64 mul2(u64 a, u64 b) {
    u64 d; asm("mul.rn.f32x2 %0, %1, %2;" : "=l"(d) : "l"(a), "l"(b)); return d;
}
__device__ __forceinline__ u64 relu2(u64 v) {
    float a, b; upk2(v, a, b);
    return pk2(fmaxf(a, 0.0f), fmaxf(b, 0.0f));
}

// ---------------------------------------------------------------------------
// Kernel 1: per-pixel MLP, 4 pixels per thread, f32x2 packed math.
// (R8 version — measured ~17.0us; issue/rt-bound, amortization beats occupancy)
// sim = w_sim . relu( bn1(W1 . relu( bn0(W0 . x) )) ) + b_sim
// ---------------------------------------------------------------------------
__global__ __launch_bounds__(256)
void mlp_sim_kernel(const float* __restrict__ x1,
                    const float* __restrict__ w0,
                    const float* __restrict__ bn0_scale,
                    const float* __restrict__ bn0_bias,
                    const float* __restrict__ w1,
                    const float* __restrict__ bn1_scale,
                    const float* __restrict__ bn1_bias,
                    const float* __restrict__ w_sim,
                    const float* __restrict__ b_sim)
{
    // sw0p[o*8+g]  = dup2( w0[o][g]  * bn0_scale[o] )   (g contiguous)
    // sw1p[o*8+k]  = dup2( w1[k][o]  * bn1_scale[k] )   (k contiguous)
    __shared__ __align__(16) u64 sw0p[16*8];
    __shared__ __align__(16) u64 sw1p[16*8];
    __shared__ float sb0[16];
    __shared__ float sb1[8];
    __shared__ float sws[8];
    __shared__ float sbs;

    const int t = threadIdx.x;
    if (t < 128) {
        float v = w0[t] * bn0_scale[t >> 3];     // t = o*8+g
        sw0p[t] = pk2(v, v);
    } else {
        int i = t - 128;                         // i = o*8+k
        int o = i >> 3, k = i & 7;
        float v = w1[k * 16 + o] * bn1_scale[k];
        sw1p[i] = pk2(v, v);
    }
    if (t < 16)       sb0[t] = bn0_bias[t];
    else if (t < 24)  sb1[t - 16] = bn1_bias[t - 16];
    else if (t < 32)  sws[t - 24] = w_sim[t - 24];
    else if (t == 32) sbs = b_sim[0];
    __syncthreads();

    const int idx4 = (blockIdx.x * 256 + t) * 4;     // N1_ multiple of 1024
    const int b = idx4 / DHW_;                       // 4 pixels share b (DHW_%4==0)
    const int base = idx4 + b * (G_ - 1) * DHW_;     // x1 flat idx of (b,g=0,pix)

    const float4* __restrict__ x4 = (const float4*)x1;

    u64 xp[2][G_];
#pragma unroll
    for (int g = 0; g < G_; g++) {
        float4 v = __ldg(&x4[(base + g * DHW_) >> 2]);
        xp[0][g] = pk2(v.x, v.y);
        xp[1][g] = pk2(v.z, v.w);
    }

    u64 h1p[2][8];
#pragma unroll
    for (int k = 0; k < 8; k++) {
        u64 bb = pk2(sb1[k], sb1[k]);
        h1p[0][k] = bb; h1p[1][k] = bb;
    }

#pragma unroll
    for (int o = 0; o < 16; o++) {
        u64 a0 = pk2(sb0[o], sb0[o]);
        u64 a1 = a0;
#pragma unroll
        for (int g = 0; g < G_; g += 2) {
            ulonglong2 wv = *(const ulonglong2*)&sw0p[o * 8 + g];  // LDS.128
            a0 = fma2(wv.x, xp[0][g],     a0);
            a1 = fma2(wv.x, xp[1][g],     a1);
            a0 = fma2(wv.y, xp[0][g + 1], a0);
            a1 = fma2(wv.y, xp[1][g + 1], a1);
        }
        a0 = relu2(a0);
        a1 = relu2(a1);
#pragma unroll
        for (int k = 0; k < 8; k += 2) {
            ulonglong2 wv = *(const ulonglong2*)&sw1p[o * 8 + k];  // LDS.128
            h1p[0][k]     = fma2(wv.x, a0, h1p[0][k]);
            h1p[1][k]     = fma2(wv.x, a1, h1p[1][k]);
            h1p[0][k + 1] = fma2(wv.y, a0, h1p[0][k + 1]);
            h1p[1][k + 1] = fma2(wv.y, a1, h1p[1][k + 1]);
        }
    }

    float s[4];
#pragma unroll
    for (int p = 0; p < 2; p++) {
        float s_lo = sbs, s_hi = sbs;
#pragma unroll
        for (int k = 0; k < 8; k++) {
            float lo, hi; upk2(h1p[p][k], lo, hi);
            s_lo = fmaf(sws[k], fmaxf(lo, 0.0f), s_lo);
            s_hi = fmaf(sws[k], fmaxf(hi, 0.0f), s_hi);
        }
        s[p * 2]     = s_lo;
        s[p * 2 + 1] = s_hi;
    }
    ((float4*)g_sim)[idx4 >> 2] = make_float4(s[0], s[1], s[2], s[3]);
}

// ---------------------------------------------------------------------------
// Kernel 2: smem-tiled two-scale 3x3 reflect stencil.
// Block = (b, 4 d-slices, 8 rows x full W). The sim tile (+4 halo on every
// side, reflect-resolved at load) lives in smem; all 72 taps per pixel-pair
// are LDS.64. Offset loads amortized over 4 d-slices. No edge path.
// ---------------------------------------------------------------------------
#define HT 8                 // output rows per block
#define DT 4                 // d-slices per block
#define TR (HT + 8)          // tile rows incl. halo = 16
#define TW (W_ + 8)          // tile cols incl. halo = 168

__device__ __forceinline__ int reflect_idx(int k, int n) {
    if (k < 0) return -k;
    if (k >= n) return 2 * n - 2 - k;
    return k;
}

__global__ __launch_bounds__(256)
void stencil_kernel(const float* __restrict__ offset,
                    const float* __restrict__ weight,
                    float* __restrict__ out)
{
    __shared__ __align__(16) float s_sim[DT][TR][TW];   // 43008 B

    // 256 blocks: b (2) x dgroup (8) x htile (16)
    const int bx  = blockIdx.x;
    const int b   = bx >> 7;            // /128
    const int rem = bx & 127;
    const int dg  = rem >> 4;
    const int h0  = (rem & 15) * HT;
    const int d0  = dg * DT;

    const int tid  = threadIdx.x;
    const int wid  = tid >> 5;
    const int lane = tid & 31;

    // ---- load tile with reflected halo (y and x resolved here) ----
    const float* __restrict__ simb = g_sim + (b * D_ + d0) * HW_;
#pragma unroll
    for (int dt = 0; dt < DT; dt++) {
#pragma unroll
        for (int r = 0; r < TR; r += 8) {          // 8 warps cover 16 rows
            const int rr = r + wid;
            const int gr = reflect_idx(h0 + rr - 4, H_);
            const float* __restrict__ src = simb + dt * HW_ + gr * W_;
            for (int c = lane; c < TW; c += 32)
                s_sim[dt][rr][c] = __ldg(&src[reflect_idx(c - 4, W_)]);
        }
    }
    __syncthreads();

    const u64* __restrict__ off64 = (const u64*)offset;
    u64* __restrict__ out64 = (u64*)out;

    // ---- compute: pixel pairs (w0, w0+1), w0 even ----
    for (int p = tid; p < HT * (W_ / 2); p += 256) {
        const int pr = p / (W_ / 2);
        const int pc = p - pr * (W_ / 2);
        const int w0 = pc * 2;
        const int hw = (h0 + pr) * W_ + w0;

        const int obase = (b * 18 * HW_ + hw) >> 1;     // u64 index (hw even)
        u64 wN[9], wW[9];
#pragma unroll
        for (int s = 0; s < 9; s++) {
            wW[s] = __ldg(&off64[obase + s * (HW_ / 2)]);
            wN[s] = __ldg(&off64[obase + (s + 9) * (HW_ / 2)]);
        }
        u64 wgt2;
        {
            float g0, g1;
            upk2(__ldg(&((const u64*)weight)[(b * HW_ + hw) >> 1]), g0, g1);
            wgt2 = pk2(0.5f * g0, 0.5f * g1);
        }

        u64 acc[DT];
#pragma unroll
        for (int dd = 0; dd < DT; dd++) acc[dd] = 0ULL;

#pragma unroll
        for (int iy = 0; iy < 3; iy++) {
            const int r1 = 4 + pr + 2 * (iy - 1);
            const int r2 = 4 + pr + 4 * (iy - 1);
#pragma unroll
            for (int ix = 0; ix < 3; ix++) {
                const int s  = iy * 3 + ix;
                const int c1 = (4 + w0 + 2 * (ix - 1)) >> 1;  // u64 col, even float idx
                const int c2 = (4 + w0 + 4 * (ix - 1)) >> 1;
#pragma unroll
                for (int dd = 0; dd < DT; dd++) {
                    const u64* __restrict__ row1 = (const u64*)&s_sim[dd][r1][0];
                    const u64* __restrict__ row2 = (const u64*)&s_sim[dd][r2][0];
                    acc[dd] = fma2(wN[s], row1[c1], acc[dd]);
                    acc[dd] = fma2(wW[s], row2[c2], acc[dd]);
                }
            }
        }
#pragma unroll
        for (int dd = 0; dd < DT; dd++)
            out64[((b * D_ + d0 + dd) * HW_ + hw) >> 1] = mul2(acc[dd], wgt2);
    }
}

// ---------------------------------------------------------------------------
// Launch
// ---------------------------------------------------------------------------
extern "C" void kernel_launch(void* const* d_in, const int* in_sizes, int n_in,
                              void* d_out, int out_size)
{
    const float* x1        = (const float*)d_in[0];
    const float* offset    = (const float*)d_in[1];
    const float* weight    = (const float*)d_in[2];
    const float* w0        = (const float*)d_in[3];
    const float* bn0_scale = (const float*)d_in[4];
    const float* bn0_bias  = (const float*)d_in[5];
    const float* w1        = (const float*)d_in[6];
    const float* bn1_scale = (const float*)d_in[7];
    const float* bn1_bias  = (const float*)d_in[8];
    const float* w_sim     = (const float*)d_in[9];
    const float* b_sim     = (const float*)d_in[10];
    float* out = (float*)d_out;

    // Kernel 1: 4 pixels/thread -> 327,680 threads, grid 1280
    mlp_sim_kernel<<<N1_ / (256 * 4), 256>>>(x1, w0, bn0_scale, bn0_bias,
                                             w1, bn1_scale, bn1_bias, w_sim, b_sim);

    // Kernel 2: B * (D/DT) * (H/HT) = 2*8*16 = 256 blocks, 256 threads
    const int n2 = B_ * (D_ / DT) * (H_ / HT);
    stencil_kernel<<<n2, 256>>>(offset, weight, out);
}

// round 13
// speedup vs baseline: 1.2503x; 1.2492x over previous
#include <cuda_runtime.h>
#include <cuda_bf16.h>

// Problem dims (fixed by the reference):
// B=2, G=8, D=32, H=128, W=160, NEIGH=9 (3x3), PAD1=2, PAD2=4
#define B_  2
#define G_  8
#define D_  32
#define H_  128
#define W_  160
#define HW_ (H_*W_)          // 20480
#define DHW_ (D_*HW_)        // 655360
#define N1_ (B_*DHW_)        // 1310720  (sim / output elements)
#define PW_ 168              // padded sim row: 4 reflected cols each side

typedef unsigned long long u64;

// x-padded similarity map (B, D, H, PW_) fp32 = 5.5 MB
__device__ float g_simp[B_*D_*H_*PW_];

// ---------------------------------------------------------------------------
// Packed f32x2 helpers (Blackwell sm_103a)
// ---------------------------------------------------------------------------
__device__ __forceinline__ u64 pk2(float lo, float hi) {
    u64 r; asm("mov.b64 %0, {%1, %2};" : "=l"(r) : "f"(lo), "f"(hi)); return r;
}
__device__ __forceinline__ void upk2(u64 v, float& lo, float& hi) {
    asm("mov.b64 {%0, %1}, %2;" : "=f"(lo), "=f"(hi) : "l"(v));
}
__device__ __forceinline__ u64 fma2(u64 a, u64 b, u64 c) {
    u64 d; asm("fma.rn.f32x2 %0, %1, %2, %3;" : "=l"(d) : "l"(a), "l"(b), "l"(c)); return d;
}
__device__ __forceinline__ u64 mul2(u64 a, u64 b) {
    u64 d; asm("mul.rn.f32x2 %0, %1, %2;" : "=l"(d) : "l"(a), "l"(b)); return d;
}
__device__ __forceinline__ u64 relu2(u64 v) {
    float a, b; upk2(v, a, b);
    return pk2(fmaxf(a, 0.0f), fmaxf(b, 0.0f));
}

// ---------------------------------------------------------------------------
// Kernel 1: per-pixel MLP, 4 pixels per thread, f32x2 packed math.
// (R8 compute — near the f32x2 ceiling.) Stores into the x-padded sim buffer,
// materializing the 4 reflected columns on each side.
// ---------------------------------------------------------------------------
__global__ __launch_bounds__(256)
void mlp_sim_kernel(const float* __restrict__ x1,
                    const float* __restrict__ w0,
                    const float* __restrict__ bn0_scale,
                    const float* __restrict__ bn0_bias,
                    const float* __restrict__ w1,
                    const float* __restrict__ bn1_scale,
                    const float* __restrict__ bn1_bias,
                    const float* __restrict__ w_sim,
                    const float* __restrict__ b_sim)
{
    __shared__ __align__(16) u64 sw0p[16*8];   // dup2(w0[o][g]*bn0_scale[o]), g contiguous
    __shared__ __align__(16) u64 sw1p[16*8];   // dup2(w1[k][o]*bn1_scale[k]), k contiguous
    __shared__ float sb0[16];
    __shared__ float sb1[8];
    __shared__ float sws[8];
    __shared__ float sbs;

    const int t = threadIdx.x;
    if (t < 128) {
        float v = w0[t] * bn0_scale[t >> 3];     // t = o*8+g
        sw0p[t] = pk2(v, v);
    } else {
        int i = t - 128;                         // i = o*8+k
        int o = i >> 3, k = i & 7;
        float v = w1[k * 16 + o] * bn1_scale[k];
        sw1p[i] = pk2(v, v);
    }
    if (t < 16)       sb0[t] = bn0_bias[t];
    else if (t < 24)  sb1[t - 16] = bn1_bias[t - 16];
    else if (t < 32)  sws[t - 24] = w_sim[t - 24];
    else if (t == 32) sbs = b_sim[0];
    __syncthreads();

    const int idx4 = (blockIdx.x * 256 + t) * 4;     // N1_ multiple of 1024
    const int b = idx4 / DHW_;                       // 4 pixels share b
    const int base = idx4 + b * (G_ - 1) * DHW_;     // x1 flat idx of (b,g=0,pix)

    const float4* __restrict__ x4 = (const float4*)x1;

    u64 xp[2][G_];
#pragma unroll
    for (int g = 0; g < G_; g++) {
        float4 v = __ldg(&x4[(base + g * DHW_) >> 2]);
        xp[0][g] = pk2(v.x, v.y);
        xp[1][g] = pk2(v.z, v.w);
    }

    u64 h1p[2][8];
#pragma unroll
    for (int k = 0; k < 8; k++) {
        u64 bb = pk2(sb1[k], sb1[k]);
        h1p[0][k] = bb; h1p[1][k] = bb;
    }

#pragma unroll
    for (int o = 0; o < 16; o++) {
        u64 a0 = pk2(sb0[o], sb0[o]);
        u64 a1 = a0;
#pragma unroll
        for (int g = 0; g < G_; g += 2) {
            ulonglong2 wv = *(const ulonglong2*)&sw0p[o * 8 + g];  // LDS.128
            a0 = fma2(wv.x, xp[0][g],     a0);
            a1 = fma2(wv.x, xp[1][g],     a1);
            a0 = fma2(wv.y, xp[0][g + 1], a0);
            a1 = fma2(wv.y, xp[1][g + 1], a1);
        }
        a0 = relu2(a0);
        a1 = relu2(a1);
#pragma unroll
        for (int k = 0; k < 8; k += 2) {
            ulonglong2 wv = *(const ulonglong2*)&sw1p[o * 8 + k];  // LDS.128
            h1p[0][k]     = fma2(wv.x, a0, h1p[0][k]);
            h1p[1][k]     = fma2(wv.x, a1, h1p[1][k]);
            h1p[0][k + 1] = fma2(wv.y, a0, h1p[0][k + 1]);
            h1p[1][k + 1] = fma2(wv.y, a1, h1p[1][k + 1]);
        }
    }

    float s[4];
#pragma unroll
    for (int p = 0; p < 2; p++) {
        float s_lo = sbs, s_hi = sbs;
#pragma unroll
        for (int k = 0; k < 8; k++) {
            float lo, hi; upk2(h1p[p][k], lo, hi);
            s_lo = fmaf(sws[k], fmaxf(lo, 0.0f), s_lo);
            s_hi = fmaf(sws[k], fmaxf(hi, 0.0f), s_hi);
        }
        s[p * 2]     = s_lo;
        s[p * 2 + 1] = s_hi;
    }

    // ---- store into padded layout (row = d*H+h within b) ----
    const int rest = idx4 - b * DHW_;
    const int row  = rest / W_;
    const int w    = rest - row * W_;          // multiple of 4
    float* __restrict__ rowbase = g_simp + (size_t)(b * D_ * H_ + row) * PW_;
    *(float4*)(rowbase + 4 + w) = make_float4(s[0], s[1], s[2], s[3]);

    // mirror columns: left pad pc=4-w' for w' in 1..4; right pad pc=322-w' for w' in 155..158
    if (w == 0) {
        rowbase[3] = s[1]; rowbase[2] = s[2]; rowbase[1] = s[3];
    } else if (w == 4) {
        rowbase[0] = s[0];
    } else if (w == 152) {
        rowbase[167] = s[3];
    } else if (w == 156) {
        rowbase[166] = s[0]; rowbase[165] = s[1]; rowbase[164] = s[2];
    }
}

// ---------------------------------------------------------------------------
// Kernel 2: register-window two-scale 3x3 stencil, no edge path.
// Thread = (b, 4 d-slices, h, 4-pixel group w0..w0+3). Per tap row: one
// 12-float window (3 LDG.128) feeds all narrow AND wide taps of all 4 pixels
// as aligned u64 extracts. Weights loaded as float4 (4 pixels per load).
// ---------------------------------------------------------------------------
__device__ __forceinline__ int reflect_idx(int k, int n) {
    if (k < 0) return -k;
    if (k >= n) return 2 * n - 2 - k;
    return k;
}

__global__ __launch_bounds__(128)
void stencil_kernel(const float* __restrict__ offset,
                    const float* __restrict__ weight,
                    float* __restrict__ out)
{
    const int idx = blockIdx.x * 128 + threadIdx.x;   // 81920 threads
    const int wq = idx % 40;
    int t1 = idx / 40;
    const int h  = t1 & 127;  t1 >>= 7;
    const int dg = t1 & 7;
    const int b  = t1 >> 3;
    const int w0 = wq * 4;
    const int d0 = dg * 4;

    const float4* __restrict__ off4 = (const float4*)offset;
    const int obase4 = (b * 18 * HW_ + h * W_ + w0) >> 2;

    u64 acc[4][2];
#pragma unroll
    for (int dd = 0; dd < 4; dd++) { acc[dd][0] = 0ULL; acc[dd][1] = 0ULL; }

    const float4* __restrict__ simp4 = (const float4*)g_simp;
    const int base4    = (((b * D_ + d0) * H_) * PW_ + w0) >> 2;
    const int dstride4 = (H_ * PW_) >> 2;             // 5376
    const int rstride4 = PW_ >> 2;                    // 42

    // rows dy = -4,-2,0,+2,+4 : wide on even i, narrow on i in {1,2,3}
#pragma unroll 1
    for (int i = 0; i < 5; i++) {
        const int dy = 2 * i - 4;
        const int gr = reflect_idx(h + dy, H_);
        const bool doN = (i >= 1) && (i <= 3);
        const bool doW = ((i & 1) == 0);

        u64 nw[3][2], ww[3][2];
        if (doN) {
            const int sr = i - 1;
#pragma unroll
            for (int tt = 0; tt < 3; tt++) {
                float4 v = __ldg(&off4[obase4 + (((9 + sr * 3 + tt) * HW_) >> 2)]);
                nw[tt][0] = pk2(v.x, v.y); nw[tt][1] = pk2(v.z, v.w);
            }
        }
        if (doW) {
            const int sr = i >> 1;
#pragma unroll
            for (int tt = 0; tt < 3; tt++) {
                float4 v = __ldg(&off4[obase4 + (((sr * 3 + tt) * HW_) >> 2)]);
                ww[tt][0] = pk2(v.x, v.y); ww[tt][1] = pk2(v.z, v.w);
            }
        }

        const float4* __restrict__ rowp = simp4 + base4 + gr * rstride4;
#pragma unroll
        for (int dd = 0; dd < 4; dd++) {
            const float4* __restrict__ p = rowp + dd * dstride4;
            float4 A  = __ldg(p);
            float4 Bv = __ldg(p + 1);
            float4 C  = __ldg(p + 2);
            u64 W0 = pk2(A.x,  A.y),  W1 = pk2(A.z,  A.w);
            u64 W2 = pk2(Bv.x, Bv.y), W3 = pk2(Bv.z, Bv.w);
            u64 W4 = pk2(C.x,  C.y),  W5 = pk2(C.z,  C.w);
            if (doN) {
                acc[dd][0] = fma2(nw[0][0], W1, acc[dd][0]);
                acc[dd][0] = fma2(nw[1][0], W2, acc[dd][0]);
                acc[dd][0] = fma2(nw[2][0], W3, acc[dd][0]);
                acc[dd][1] = fma2(nw[0][1], W2, acc[dd][1]);
                acc[dd][1] = fma2(nw[1][1], W3, acc[dd][1]);
                acc[dd][1] = fma2(nw[2][1], W4, acc[dd][1]);
            }
            if (doW) {
                acc[dd][0] = fma2(ww[0][0], W0, acc[dd][0]);
                acc[dd][0] = fma2(ww[1][0], W2, acc[dd][0]);
                acc[dd][0] = fma2(ww[2][0], W4, acc[dd][0]);
                acc[dd][1] = fma2(ww[0][1], W1, acc[dd][1]);
                acc[dd][1] = fma2(ww[1][1], W3, acc[dd][1]);
                acc[dd][1] = fma2(ww[2][1], W5, acc[dd][1]);
            }
        }
    }

    float4 wv = __ldg(&((const float4*)weight)[(b * HW_ + h * W_ + w0) >> 2]);
    const u64 wg0 = pk2(0.5f * wv.x, 0.5f * wv.y);
    const u64 wg1 = pk2(0.5f * wv.z, 0.5f * wv.w);

#pragma unroll
    for (int dd = 0; dd < 4; dd++) {
        u64 r0 = mul2(acc[dd][0], wg0);
        u64 r1 = mul2(acc[dd][1], wg1);
        float x0, x1, x2, x3; upk2(r0, x0, x1); upk2(r1, x2, x3);
        ((float4*)out)[((b * D_ + d0 + dd) * HW_ + h * W_ + w0) >> 2] =
            make_float4(x0, x1, x2, x3);
    }
}

// ---------------------------------------------------------------------------
// Launch
// ---------------------------------------------------------------------------
extern "C" void kernel_launch(void* const* d_in, const int* in_sizes, int n_in,
                              void* d_out, int out_size)
{
    const float* x1        = (const float*)d_in[0];
    const float* offset    = (const float*)d_in[1];
    const float* weight    = (const float*)d_in[2];
    const float* w0        = (const float*)d_in[3];
    const float* bn0_scale = (const float*)d_in[4];
    const float* bn0_bias  = (const float*)d_in[5];
    const float* w1        = (const float*)d_in[6];
    const float* bn1_scale = (const float*)d_in[7];
    const float* bn1_bias  = (const float*)d_in[8];
    const float* w_sim     = (const float*)d_in[9];
    const float* b_sim     = (const float*)d_in[10];
    float* out = (float*)d_out;

    // Kernel 1: 4 pixels/thread -> 327,680 threads, grid 1280
    mlp_sim_kernel<<<N1_ / (256 * 4), 256>>>(x1, w0, bn0_scale, bn0_bias,
                                             w1, bn1_scale, bn1_bias, w_sim, b_sim);

    // Kernel 2: B*(D/4)*H*(W/4) = 81,920 threads, grid 640
    const int n2 = B_ * (D_ / 4) * H_ * (W_ / 4);
    stencil_kernel<<<n2 / 128, 128>>>(offset, weight, out);
}